// round 2
// baseline (speedup 1.0000x reference)
#include <cuda_runtime.h>
#include <cuda_bf16.h>
#include <cstdint>

#define BB 128
#define SS 512
#define HH 128
#define NEG_INF (-9.0e15f)

// -------- static device scratch (no allocations allowed) --------
static __device__ unsigned char g_code[(size_t)BB * SS * SS];   // 33.5 MB: bit0=adj[i][j]==1, bit1=adj[j][i]==1
static __device__ float g_hbuf0[(size_t)BB * SS * HH];          // layer-1 output
static __device__ float g_hbuf1[(size_t)BB * SS * HH];          // layer-2 output
static __device__ float g_sa[BB * SS];                          // w1 . h_i + bias
static __device__ float g_sb[BB * SS];                          // w2 . h_i

// ---------------------------------------------------------------
// Kernel 1: pack adjacency into 2-bit codes (run once per launch)
// grid (S/32, S/32, B), block (32,32)
// ---------------------------------------------------------------
__global__ void pack_code_kernel(const float* __restrict__ adj) {
    __shared__ float tT[32][33];
    const int b = blockIdx.z;
    const int J = blockIdx.x * 32;
    const int I = blockIdx.y * 32;
    const int tx = threadIdx.x, ty = threadIdx.y;
    const float* A = adj + (size_t)b * SS * SS;

    // coalesced load of the transposed tile
    tT[ty][tx] = A[(size_t)(J + ty) * SS + (I + tx)];
    float a = A[(size_t)(I + ty) * SS + (J + tx)];
    __syncthreads();

    unsigned char c = (a == 1.0f ? 1u : 0u) | (tT[tx][ty] == 1.0f ? 2u : 0u);
    g_code[((size_t)b * SS + (I + ty)) * SS + (J + tx)] = c;
}

// ---------------------------------------------------------------
// Kernel 2: per-row projections sa = w1.h + bias, sb = w2.h
// one warp per row; grid = B*S/8, block 256
// ---------------------------------------------------------------
__global__ void sasb_kernel(const float* __restrict__ hin,
                            const float* __restrict__ w1,
                            const float* __restrict__ w2,
                            const float* __restrict__ bias_ptr) {
    const int tid  = threadIdx.x;
    const int lane = tid & 31;
    const int row  = blockIdx.x * 8 + (tid >> 5);
    if (row >= BB * SS) return;

    const float4 hv  = reinterpret_cast<const float4*>(hin)[(size_t)row * 32 + lane];
    const float4 w1v = reinterpret_cast<const float4*>(w1)[lane];
    const float4 w2v = reinterpret_cast<const float4*>(w2)[lane];

    float d1 = hv.x * w1v.x + hv.y * w1v.y + hv.z * w1v.z + hv.w * w1v.w;
    float d2 = hv.x * w2v.x + hv.y * w2v.y + hv.z * w2v.z + hv.w * w2v.w;
    #pragma unroll
    for (int off = 16; off > 0; off >>= 1) {
        d1 += __shfl_xor_sync(0xFFFFFFFFu, d1, off);
        d2 += __shfl_xor_sync(0xFFFFFFFFu, d2, off);
    }
    if (lane == 0) {
        g_sa[row] = d1 + bias_ptr[0];   // bias folded into sa
        g_sb[row] = d2;
    }
}

// ---------------------------------------------------------------
// Kernel 3: fused masked-score + softmax + (P @ hidden)
// grid (S/32, B), block 256 (8 warps). Each block: 32 output rows.
// smem: sa[512] | sb[512] | P[32][512] | Htile[32][128]  = 84 KB
// ---------------------------------------------------------------
#define FUSED_SMEM_BYTES ((2 * SS + 32 * SS + 32 * HH) * sizeof(float))

__global__ __launch_bounds__(256, 1)
void fused_layer_kernel(const float* __restrict__ hin,
                        float* __restrict__ hout) {
    extern __shared__ float smem[];
    float* s_sa = smem;                 // [512]
    float* s_sb = smem + SS;            // [512]
    float* s_p  = smem + 2 * SS;        // [32][512]
    float* s_h  = smem + 2 * SS + 32 * SS; // [32][128]

    const int b   = blockIdx.y;
    const int i0  = blockIdx.x * 32;
    const int tid = threadIdx.x;
    const int w   = tid >> 5;
    const int lane = tid & 31;

    // stage per-row scalars for this batch
    #pragma unroll
    for (int q = 0; q < 2; q++) {
        int j = q * 256 + tid;
        s_sa[j] = g_sa[b * SS + j];
        s_sb[j] = g_sb[b * SS + j];
    }
    __syncthreads();

    // ---- Phase P: each warp computes 4 rows of masked scores + softmax ----
    #pragma unroll
    for (int r = 0; r < 4; r++) {
        const int ii = i0 + w * 4 + r;                 // row within batch
        const float sai = s_sa[ii];
        const float sbi = s_sb[ii];
        const unsigned char* crow = g_code + ((size_t)b * SS + ii) * SS;

        float vals[16];
        float mx = NEG_INF;
        #pragma unroll
        for (int k = 0; k < 16; k++) {
            const int j = (k << 5) + lane;
            const unsigned int c = crow[j];
            float v;
            if (c == 0u) {
                v = NEG_INF;
            } else {
                const float t1 = tanhf(sai + s_sb[j]);
                const float t2 = tanhf(s_sa[j] + sbi);
                const float m1 = (c & 1u) ? 1.0f : 0.0f;
                const float m2 = (c & 2u) ? 1.0f : 0.0f;
                v = 0.5f * (m1 * t1 + m2 * t2);
            }
            vals[k] = v;
            mx = fmaxf(mx, v);
        }
        #pragma unroll
        for (int off = 16; off > 0; off >>= 1)
            mx = fmaxf(mx, __shfl_xor_sync(0xFFFFFFFFu, mx, off));

        float s = 0.0f;
        #pragma unroll
        for (int k = 0; k < 16; k++) {
            vals[k] = __expf(vals[k] - mx);
            s += vals[k];
        }
        #pragma unroll
        for (int off = 16; off > 0; off >>= 1)
            s += __shfl_xor_sync(0xFFFFFFFFu, s, off);
        const float inv = 1.0f / s;

        float* prow = s_p + (w * 4 + r) * SS;
        #pragma unroll
        for (int k = 0; k < 16; k++)
            prow[(k << 5) + lane] = vals[k] * inv;
    }
    __syncthreads();

    // ---- Phase B: out[32][128] = P[32][512] @ hidden[b][512][128] ----
    const int tx = lane;          // 32 col-groups (float4 each)
    const int ty = w;             // 8 row-groups of 4
    const float4* h4 = reinterpret_cast<const float4*>(hin + (size_t)b * SS * HH);
    float4* s_h4 = reinterpret_cast<float4*>(s_h);

    float acc[4][4];
    #pragma unroll
    for (int r = 0; r < 4; r++)
        #pragma unroll
        for (int c = 0; c < 4; c++) acc[r][c] = 0.0f;

    for (int j0 = 0; j0 < SS; j0 += 32) {
        // load hidden tile [32][128] as 1024 float4, 4 per thread
        #pragma unroll
        for (int q = 0; q < 4; q++) {
            const int lin = q * 256 + tid;
            const int row = lin >> 5;
            const int c4  = lin & 31;
            s_h4[lin] = h4[(size_t)(j0 + row) * 32 + c4];
        }
        __syncthreads();

        #pragma unroll
        for (int jj = 0; jj < 32; jj++) {
            const float4 hv = s_h4[jj * 32 + tx];
            float pv[4];
            #pragma unroll
            for (int r = 0; r < 4; r++)
                pv[r] = s_p[(ty * 4 + r) * SS + j0 + jj];   // broadcast
            #pragma unroll
            for (int r = 0; r < 4; r++) {
                acc[r][0] += pv[r] * hv.x;
                acc[r][1] += pv[r] * hv.y;
                acc[r][2] += pv[r] * hv.z;
                acc[r][3] += pv[r] * hv.w;
            }
        }
        __syncthreads();
    }

    float* outb = hout + (size_t)b * SS * HH;
    #pragma unroll
    for (int r = 0; r < 4; r++) {
        const int ii = i0 + ty * 4 + r;
        reinterpret_cast<float4*>(outb)[(size_t)ii * 32 + tx] =
            make_float4(acc[r][0], acc[r][1], acc[r][2], acc[r][3]);
    }
}

// ---------------------------------------------------------------
// Kernel 4: gather rows by alias_inputs (float4 granularity)
// ---------------------------------------------------------------
__global__ void gather_kernel(const float* __restrict__ hfin,
                              const int* __restrict__ alias,
                              float* __restrict__ out) {
    const int tid = blockIdx.x * blockDim.x + threadIdx.x;
    const int N4 = BB * SS * (HH / 4);
    if (tid >= N4) return;
    const int c4 = tid & 31;
    const int s  = (tid >> 5) & (SS - 1);
    const int b  = tid >> (5 + 9);
    const int a  = alias[b * SS + s];
    reinterpret_cast<float4*>(out)[tid] =
        reinterpret_cast<const float4*>(hfin)[((size_t)b * SS + a) * 32 + c4];
}

// ---------------------------------------------------------------
extern "C" void kernel_launch(void* const* d_in, const int* in_sizes, int n_in,
                              void* d_out, int out_size) {
    const float* hidden = (const float*)d_in[0];
    const float* adj    = (const float*)d_in[1];
    const int*   alias  = (const int*)d_in[2];
    const float* w1     = (const float*)d_in[3];
    const float* w2     = (const float*)d_in[4];
    const float* bias   = (const float*)d_in[5];
    float* out = (float*)d_out;

    cudaFuncSetAttribute(fused_layer_kernel,
                         cudaFuncAttributeMaxDynamicSharedMemorySize,
                         (int)FUSED_SMEM_BYTES);

    float* hb0;  cudaGetSymbolAddress((void**)&hb0, g_hbuf0);
    float* hb1;  cudaGetSymbolAddress((void**)&hb1, g_hbuf1);

    // 1. pack adjacency codes (layer-invariant)
    pack_code_kernel<<<dim3(SS / 32, SS / 32, BB), dim3(32, 32)>>>(adj);

    // 2. two aggregation layers
    const float* cur = hidden;
    float* nxt = hb0;
    for (int l = 0; l < 2; l++) {
        sasb_kernel<<<(BB * SS) / 8, 256>>>(cur, w1, w2, bias);
        fused_layer_kernel<<<dim3(SS / 32, BB), 256, FUSED_SMEM_BYTES>>>(cur, nxt);
        cur = nxt;
        nxt = hb1;
    }

    // 3. gather by alias_inputs
    const int N4 = BB * SS * (HH / 4);
    gather_kernel<<<(N4 + 255) / 256, 256>>>(cur, alias, out);
}

// round 3
// speedup vs baseline: 1.3680x; 1.3680x over previous
#include <cuda_runtime.h>
#include <cuda_bf16.h>
#include <cstdint>

#define BB 128
#define SS 512
#define HH 128
#define NEG_INF (-9.0e15f)
#define EPSM 8.673617379884035e-19f   // 2^-60, exact in bf16

// -------- static device scratch (no allocations allowed) --------
static __device__ unsigned char g_code[(size_t)BB * SS * SS];   // bit0=adj[i][j]==1, bit1=adj[j][i]==1
static __device__ float g_hbuf0[(size_t)BB * SS * HH];
static __device__ float g_hbuf1[(size_t)BB * SS * HH];
static __device__ float g_sa[BB * SS];                          // w1.h + bias
static __device__ float g_sb[BB * SS];                          // w2.h

// ---------------- FMA-pipe transcendentals (no MUFU) ----------------
__device__ __forceinline__ float fast_rcp(float d) {
    float r = __int_as_float(0x7EF311C3u - __float_as_int(d));
    r = r * (2.0f - d * r);
    r = r * (2.0f - d * r);
    return r;
}
__device__ __forceinline__ float fast_tanh(float x) {
    x = fminf(fmaxf(x, -9.0f), 9.0f);
    const float x2 = x * x;
    float p = -2.76076847742355e-16f;
    p = fmaf(p, x2, 2.00018790482477e-13f);
    p = fmaf(p, x2, -8.60467152213735e-11f);
    p = fmaf(p, x2, 5.12229709037114e-08f);
    p = fmaf(p, x2, 1.48572235717979e-05f);
    p = fmaf(p, x2, 6.37261928875436e-04f);
    p = fmaf(p, x2, 4.89352455891786e-03f);
    p = p * x;
    float q = 1.19825839466702e-06f;
    q = fmaf(q, x2, 1.18534705686654e-04f);
    q = fmaf(q, x2, 2.26843463243900e-03f);
    q = fmaf(q, x2, 4.89352518554385e-03f);
    return p * fast_rcp(q);
}
// exp(v) for v in [-1.01, 1.01]: Taylor deg-8, abs err < 8e-6
__device__ __forceinline__ float fast_exp_pm1(float v) {
    float p = 2.48015873e-5f;
    p = fmaf(p, v, 1.98412698e-4f);
    p = fmaf(p, v, 1.38888889e-3f);
    p = fmaf(p, v, 8.33333333e-3f);
    p = fmaf(p, v, 4.16666667e-2f);
    p = fmaf(p, v, 0.166666667f);
    p = fmaf(p, v, 0.5f);
    p = fmaf(p, v, 1.0f);
    p = fmaf(p, v, 1.0f);
    return p;
}

// ---------------- tensor-core primitives ----------------
__device__ __forceinline__ void ldsm_x4(uint32_t r[4], uint32_t addr) {
    asm volatile("ldmatrix.sync.aligned.m8n8.x4.shared.b16 {%0,%1,%2,%3}, [%4];"
        : "=r"(r[0]), "=r"(r[1]), "=r"(r[2]), "=r"(r[3]) : "r"(addr));
}
__device__ __forceinline__ void ldsm_x4_t(uint32_t r[4], uint32_t addr) {
    asm volatile("ldmatrix.sync.aligned.m8n8.x4.trans.shared.b16 {%0,%1,%2,%3}, [%4];"
        : "=r"(r[0]), "=r"(r[1]), "=r"(r[2]), "=r"(r[3]) : "r"(addr));
}
__device__ __forceinline__ void mma16816(float acc[4], const uint32_t a[4],
                                         uint32_t b0, uint32_t b1) {
    asm volatile(
        "mma.sync.aligned.m16n8k16.row.col.f32.bf16.bf16.f32 "
        "{%0,%1,%2,%3}, {%4,%5,%6,%7}, {%8,%9}, {%0,%1,%2,%3};\n"
        : "+f"(acc[0]), "+f"(acc[1]), "+f"(acc[2]), "+f"(acc[3])
        : "r"(a[0]), "r"(a[1]), "r"(a[2]), "r"(a[3]), "r"(b0), "r"(b1));
}
__device__ __forceinline__ uint32_t bfbits(__nv_bfloat16 v) {
    return (uint32_t)__bfloat16_as_ushort(v);
}

// ---------------------------------------------------------------
// Kernel 1: pack adjacency into 2-bit codes
// ---------------------------------------------------------------
__global__ void pack_code_kernel(const float* __restrict__ adj) {
    __shared__ float tT[32][33];
    const int b = blockIdx.z;
    const int J = blockIdx.x * 32;
    const int I = blockIdx.y * 32;
    const int tx = threadIdx.x, ty = threadIdx.y;
    const float* A = adj + (size_t)b * SS * SS;

    tT[ty][tx] = A[(size_t)(J + ty) * SS + (I + tx)];
    float a = A[(size_t)(I + ty) * SS + (J + tx)];
    __syncthreads();

    unsigned char c = (a == 1.0f ? 1u : 0u) | (tT[tx][ty] == 1.0f ? 2u : 0u);
    g_code[((size_t)b * SS + (I + ty)) * SS + (J + tx)] = c;
}

// ---------------------------------------------------------------
// Kernel 2: sa = w1.h + bias, sb = w2.h  (one warp per row)
// ---------------------------------------------------------------
__global__ void sasb_kernel(const float* __restrict__ hin,
                            const float* __restrict__ w1,
                            const float* __restrict__ w2,
                            const float* __restrict__ bias_ptr) {
    const int tid  = threadIdx.x;
    const int lane = tid & 31;
    const int row  = blockIdx.x * 8 + (tid >> 5);
    if (row >= BB * SS) return;

    const float4 hv  = reinterpret_cast<const float4*>(hin)[(size_t)row * 32 + lane];
    const float4 w1v = reinterpret_cast<const float4*>(w1)[lane];
    const float4 w2v = reinterpret_cast<const float4*>(w2)[lane];

    float d1 = hv.x * w1v.x + hv.y * w1v.y + hv.z * w1v.z + hv.w * w1v.w;
    float d2 = hv.x * w2v.x + hv.y * w2v.y + hv.z * w2v.z + hv.w * w2v.w;
    #pragma unroll
    for (int off = 16; off > 0; off >>= 1) {
        d1 += __shfl_xor_sync(0xFFFFFFFFu, d1, off);
        d2 += __shfl_xor_sync(0xFFFFFFFFu, d2, off);
    }
    if (lane == 0) {
        g_sa[row] = d1 + bias_ptr[0];
        g_sb[row] = d2;
    }
}

// ---------------------------------------------------------------
// Kernel 3: fused scores + softmax(no-max, eps trick) + bf16-split MMA
// block = 256 thr (8 warps), handles (batch b, 64 rows). grid (8, 128).
// ---------------------------------------------------------------
#define LDP 520   // P row stride in bf16 (512 + 8 pad -> 16B shift per row)
#define LDH 136   // H chunk row stride in bf16 (128 + 8 pad)

#define OFF_SA   0
#define OFF_SB   2048
#define OFF_RSUM 4096
#define OFF_PHI  4352
#define OFF_PLO  (OFF_PHI + 64 * LDP * 2)          // +66560
#define OFF_HHI  (OFF_PLO + 64 * LDP * 2)
#define OFF_HLO  (OFF_HHI + 64 * LDH * 2)
#define SMEM_TOTAL (OFF_HLO + 64 * LDH * 2)        // 172288 bytes

__global__ __launch_bounds__(256, 1)
void fused_layer_kernel(const float* __restrict__ hin,
                        float* __restrict__ hout) {
    extern __shared__ char smem[];
    float* s_sa   = (float*)(smem + OFF_SA);
    float* s_sb   = (float*)(smem + OFF_SB);
    float* s_rsum = (float*)(smem + OFF_RSUM);
    const uint32_t smem_u32 = (uint32_t)__cvta_generic_to_shared(smem);

    const int b   = blockIdx.y;
    const int i0  = blockIdx.x * 64;
    const int tid = threadIdx.x;
    const int lane = tid & 31;
    const int w    = tid >> 5;

    // ---- stage per-row scalars ----
    #pragma unroll
    for (int q = 0; q < 2; q++) {
        int j = q * 256 + tid;
        s_sa[j] = g_sa[b * SS + j];
        s_sb[j] = g_sb[b * SS + j];
    }
    __syncthreads();

    // ---- Phase E: scores -> exp -> bf16 hi/lo into smem P, plus row sums ----
    {
        const int r   = tid >> 2;          // local row 0..63
        const int sub = tid & 3;           // 4 threads per row, 128 j each
        const int gi  = i0 + r;
        const float sai = s_sa[gi];
        const float sbi = s_sb[gi];
        const unsigned char* crow = g_code + ((size_t)b * SS + gi) * SS + sub * 128;
        uint2* phrow = (uint2*)(smem + OFF_PHI + (r * LDP + sub * 128) * 2);
        uint2* plrow = (uint2*)(smem + OFF_PLO + (r * LDP + sub * 128) * 2);

        float esum = 0.0f;
        #pragma unroll 4
        for (int it = 0; it < 32; it++) {
            const uchar4 cc = reinterpret_cast<const uchar4*>(crow)[it];
            const int jb = sub * 128 + it * 4;
            uint32_t hp[2], lp[2];
            #pragma unroll
            for (int e4 = 0; e4 < 4; e4++) {
                const unsigned int c = (e4 == 0) ? cc.x : (e4 == 1) ? cc.y
                                      : (e4 == 2) ? cc.z : cc.w;
                const int j = jb + e4;
                const float t1 = fast_tanh(sai + s_sb[j]);
                const float t2 = fast_tanh(s_sa[j] + sbi);
                const float f1 = (c & 1u) ? t1 : 0.0f;
                const float f2 = (c & 2u) ? t2 : 0.0f;
                float e = fast_exp_pm1(0.5f * (f1 + f2));
                e = c ? e : EPSM;
                esum += e;
                const __nv_bfloat16 hi = __float2bfloat16_rn(e);
                const __nv_bfloat16 lo = __float2bfloat16_rn(e - __bfloat162float(hi));
                const uint32_t hb = bfbits(hi), lb = bfbits(lo);
                if (e4 & 1) { hp[e4 >> 1] |= hb << 16; lp[e4 >> 1] |= lb << 16; }
                else        { hp[e4 >> 1]  = hb;       lp[e4 >> 1]  = lb;       }
            }
            phrow[it] = make_uint2(hp[0], hp[1]);
            plrow[it] = make_uint2(lp[0], lp[1]);
        }
        esum += __shfl_xor_sync(0xFFFFFFFFu, esum, 1);
        esum += __shfl_xor_sync(0xFFFFFFFFu, esum, 2);
        if (sub == 0) s_rsum[r] = esum;
    }
    __syncthreads();

    // ---- Phase B: acc[64x128] = P_split @ H_split, K-chunked by 64 ----
    const int mi = w & 3;          // M tile (16 rows each)
    const int ni = w >> 2;         // N half (64 cols each)
    const int m0 = mi * 16;
    const uint32_t a_off  = ((uint32_t)(m0 + (lane & 15)) * LDP + (lane >> 4) * 8) * 2;
    const uint32_t b_roff = ((lane >> 3) & 1) * 8 + (lane & 7);   // k row within 16
    const uint32_t b_coff = ni * 64 + (lane >> 4) * 8;
    const float4* h4 = reinterpret_cast<const float4*>(hin + (size_t)b * SS * HH);

    float acc[8][4];
    #pragma unroll
    for (int nf = 0; nf < 8; nf++)
        #pragma unroll
        for (int q = 0; q < 4; q++) acc[nf][q] = 0.0f;

    for (int kc = 0; kc < 8; kc++) {
        // stage H chunk [64 x 128] fp32 -> hi/lo bf16
        #pragma unroll
        for (int q = 0; q < 8; q++) {
            const int lin = q * 256 + tid;
            const int jj  = lin >> 5;
            const int c4  = lin & 31;
            const float4 hv = h4[(size_t)(kc * 64 + jj) * 32 + c4];
            __nv_bfloat16 h0 = __float2bfloat16_rn(hv.x);
            __nv_bfloat16 h1 = __float2bfloat16_rn(hv.y);
            __nv_bfloat16 h2 = __float2bfloat16_rn(hv.z);
            __nv_bfloat16 h3 = __float2bfloat16_rn(hv.w);
            __nv_bfloat16 l0 = __float2bfloat16_rn(hv.x - __bfloat162float(h0));
            __nv_bfloat16 l1 = __float2bfloat16_rn(hv.y - __bfloat162float(h1));
            __nv_bfloat16 l2 = __float2bfloat16_rn(hv.z - __bfloat162float(h2));
            __nv_bfloat16 l3 = __float2bfloat16_rn(hv.w - __bfloat162float(h3));
            uint2* dsth = (uint2*)(smem + OFF_HHI + (jj * LDH + c4 * 4) * 2);
            uint2* dstl = (uint2*)(smem + OFF_HLO + (jj * LDH + c4 * 4) * 2);
            *dsth = make_uint2(bfbits(h0) | (bfbits(h1) << 16),
                               bfbits(h2) | (bfbits(h3) << 16));
            *dstl = make_uint2(bfbits(l0) | (bfbits(l1) << 16),
                               bfbits(l2) | (bfbits(l3) << 16));
        }
        __syncthreads();

        #pragma unroll
        for (int ks = 0; ks < 4; ks++) {
            const int kg = kc * 64 + ks * 16;   // global k for P
            const int kl = ks * 16;             // local k for H chunk
            uint32_t ahi[4], alo[4];
            ldsm_x4(ahi, smem_u32 + OFF_PHI + a_off + kg * 2);
            ldsm_x4(alo, smem_u32 + OFF_PLO + a_off + kg * 2);
            #pragma unroll
            for (int nn = 0; nn < 4; nn++) {
                const uint32_t baddr = ((kl + b_roff) * LDH + b_coff + nn * 16) * 2;
                uint32_t bh[4], bl[4];
                ldsm_x4_t(bh, smem_u32 + OFF_HHI + baddr);
                ldsm_x4_t(bl, smem_u32 + OFF_HLO + baddr);
                mma16816(acc[2 * nn],     ahi, bh[0], bh[1]);
                mma16816(acc[2 * nn],     ahi, bl[0], bl[1]);
                mma16816(acc[2 * nn],     alo, bh[0], bh[1]);
                mma16816(acc[2 * nn + 1], ahi, bh[2], bh[3]);
                mma16816(acc[2 * nn + 1], ahi, bl[2], bl[3]);
                mma16816(acc[2 * nn + 1], alo, bh[2], bh[3]);
            }
        }
        __syncthreads();
    }

    // ---- epilogue: normalize by row sum, store fp32 ----
    const int r0 = m0 + (lane >> 2);
    const float inv0 = 1.0f / s_rsum[r0];
    const float inv1 = 1.0f / s_rsum[r0 + 8];
    float* outr0 = hout + ((size_t)b * SS + i0 + r0) * HH;
    #pragma unroll
    for (int nf = 0; nf < 8; nf++) {
        const int col = ni * 64 + nf * 8 + 2 * (lane & 3);
        *(float2*)(outr0 + col) = make_float2(acc[nf][0] * inv0, acc[nf][1] * inv0);
        *(float2*)(outr0 + 8 * HH + col) = make_float2(acc[nf][2] * inv1, acc[nf][3] * inv1);
    }
}

// ---------------------------------------------------------------
// Kernel 4: gather rows by alias_inputs
// ---------------------------------------------------------------
__global__ void gather_kernel(const float* __restrict__ hfin,
                              const int* __restrict__ alias,
                              float* __restrict__ out) {
    const int tid = blockIdx.x * blockDim.x + threadIdx.x;
    const int N4 = BB * SS * (HH / 4);
    if (tid >= N4) return;
    const int c4 = tid & 31;
    const int s  = (tid >> 5) & (SS - 1);
    const int b  = tid >> (5 + 9);
    const int a  = alias[b * SS + s];
    reinterpret_cast<float4*>(out)[tid] =
        reinterpret_cast<const float4*>(hfin)[((size_t)b * SS + a) * 32 + c4];
}

// ---------------------------------------------------------------
extern "C" void kernel_launch(void* const* d_in, const int* in_sizes, int n_in,
                              void* d_out, int out_size) {
    const float* hidden = (const float*)d_in[0];
    const float* adj    = (const float*)d_in[1];
    const int*   alias  = (const int*)d_in[2];
    const float* w1     = (const float*)d_in[3];
    const float* w2     = (const float*)d_in[4];
    const float* bias   = (const float*)d_in[5];
    float* out = (float*)d_out;

    cudaFuncSetAttribute(fused_layer_kernel,
                         cudaFuncAttributeMaxDynamicSharedMemorySize, SMEM_TOTAL);

    float* hb0;  cudaGetSymbolAddress((void**)&hb0, g_hbuf0);
    float* hb1;  cudaGetSymbolAddress((void**)&hb1, g_hbuf1);

    pack_code_kernel<<<dim3(SS / 32, SS / 32, BB), dim3(32, 32)>>>(adj);

    const float* cur = hidden;
    float* nxt = hb0;
    for (int l = 0; l < 2; l++) {
        sasb_kernel<<<(BB * SS) / 8, 256>>>(cur, w1, w2, bias);
        fused_layer_kernel<<<dim3(SS / 64, BB), 256, SMEM_TOTAL>>>(cur, nxt);
        cur = nxt;
        nxt = hb1;
    }

    const int N4 = BB * SS * (HH / 4);
    gather_kernel<<<(N4 + 255) / 256, 256>>>(cur, alias, out);
}